// round 14
// baseline (speedup 1.0000x reference)
#include <cuda_runtime.h>
#include <cuda_bf16.h>
#include <cstdint>

#define NNODES  50000
#define MAXE    800000
#define HID     128
#define INDIM   768
#define NGRAPH  128
#define NCLS    3
#define NSCANB  196             // ceil(50000/256)

// GEMM tiling: BM=128, BN=128, BK=32
#define BK      32
#define ASTRIDE 80
#define ABUF    10240           // 128 * 80
#define BBUF    10240
#define BUFSZ   40960           // 2*ABUF + 2*BBUF
#define MMA_SMEM (2 * BUFSZ)    // 81920  (plain gemm)

// fused kernel extra regions (overlapping main buffers):
// B2 double buffer [0, 40960): two bufs of 20480 (hi 10240 + lo 10240)
// T  hi [40960, 75776), lo [75776, 110592); row stride 272 (256B data + 16 pad)
#define B2BUF   20480
#define T_HI    40960
#define T_LO    75776
#define TSTRIDE 272
#define FUSED_SMEM 110592

// ---------------- scratch -------------------------------------------------
__device__ float g_h   [NNODES * HID];
__device__ float g_hs  [NNODES * HID];
__device__ float g_dinv[NNODES];
__device__ int   g_deg [NNODES];
__device__ int   g_start[NNODES + 1];
__device__ int   g_cursor[NNODES];
__device__ int   g_bsum[NSCANB];
__device__ int   g_csr [MAXE];
__device__ float g_pool[NGRAPH * HID + NGRAPH];
__device__ __nv_bfloat16 g_Wemb_h[HID * INDIM], g_Wemb_l[HID * INDIM];
__device__ __nv_bfloat16 g_Wc1_h [HID * HID],   g_Wc1_l [HID * HID];
__device__ __nv_bfloat16 g_Wc2_h [HID * HID],   g_Wc2_l [HID * HID];

// ---------------- helpers -------------------------------------------------
__device__ __forceinline__ uint32_t s2u(const void *p) {
    uint32_t a;
    asm("{ .reg .u64 t; cvta.to.shared.u64 t, %1; cvt.u32.u64 %0, t; }"
        : "=r"(a) : "l"(p));
    return a;
}
__device__ __forceinline__ void red4(float *p, float4 v) {
    asm volatile("red.global.add.v4.f32 [%0], {%1, %2, %3, %4};"
                 :: "l"(p), "f"(v.x), "f"(v.y), "f"(v.z), "f"(v.w) : "memory");
}
__device__ __forceinline__ void ldsm4(uint32_t &r0, uint32_t &r1, uint32_t &r2,
                                      uint32_t &r3, uint32_t addr) {
    asm volatile("ldmatrix.sync.aligned.m8n8.x4.shared.b16 {%0,%1,%2,%3}, [%4];"
                 : "=r"(r0), "=r"(r1), "=r"(r2), "=r"(r3) : "r"(addr));
}
__device__ __forceinline__ void mma16816(float *c, const uint32_t *a,
                                         const uint32_t *b) {
    asm volatile(
        "mma.sync.aligned.m16n8k16.row.col.f32.bf16.bf16.f32 "
        "{%0,%1,%2,%3}, {%4,%5,%6,%7}, {%8,%9}, {%0,%1,%2,%3};"
        : "+f"(c[0]), "+f"(c[1]), "+f"(c[2]), "+f"(c[3])
        : "r"(a[0]), "r"(a[1]), "r"(a[2]), "r"(a[3]), "r"(b[0]), "r"(b[1]));
}
__device__ __forceinline__ void cpa16(uint32_t s, const void *g) {
    asm volatile("cp.async.cg.shared.global [%0], [%1], 16;" :: "r"(s), "l"(g));
}
__device__ __forceinline__ void cvt8(const float4 &v0, const float4 &v1,
                                     uint4 &hv, uint4 &lv) {
    __nv_bfloat162 h0 = __floats2bfloat162_rn(v0.x, v0.y);
    __nv_bfloat162 h1 = __floats2bfloat162_rn(v0.z, v0.w);
    __nv_bfloat162 h2 = __floats2bfloat162_rn(v1.x, v1.y);
    __nv_bfloat162 h3 = __floats2bfloat162_rn(v1.z, v1.w);
    __nv_bfloat162 l0 = __floats2bfloat162_rn(v0.x - __bfloat162float(h0.x),
                                              v0.y - __bfloat162float(h0.y));
    __nv_bfloat162 l1 = __floats2bfloat162_rn(v0.z - __bfloat162float(h1.x),
                                              v0.w - __bfloat162float(h1.y));
    __nv_bfloat162 l2 = __floats2bfloat162_rn(v1.x - __bfloat162float(h2.x),
                                              v1.y - __bfloat162float(h2.y));
    __nv_bfloat162 l3 = __floats2bfloat162_rn(v1.z - __bfloat162float(h3.x),
                                              v1.w - __bfloat162float(h3.y));
    hv = make_uint4(*(uint32_t *)&h0, *(uint32_t *)&h1,
                    *(uint32_t *)&h2, *(uint32_t *)&h3);
    lv = make_uint4(*(uint32_t *)&l0, *(uint32_t *)&l1,
                    *(uint32_t *)&l2, *(uint32_t *)&l3);
}

// ---------------- misc small kernels --------------------------------------
__global__ void k_zero4(float4 *__restrict__ p, int n4) {
    int i = blockIdx.x * blockDim.x + threadIdx.x;
    if (i < n4) p[i] = make_float4(0.f, 0.f, 0.f, 0.f);
}
__global__ void k_zero_deg(int *__restrict__ p, int n) {
    int i = blockIdx.x * blockDim.x + threadIdx.x;
    if (i < n) p[i] = 0;
}
__global__ void k_deg(const int *__restrict__ ei, int E) {
    int i = blockIdx.x * blockDim.x + threadIdx.x;
    if (i < E) atomicAdd(&g_deg[ei[E + i]], 1);
}
__global__ void k_dinv(int N) {
    int i = blockIdx.x * blockDim.x + threadIdx.x;
    if (i < N) g_dinv[i] = rsqrtf((float)g_deg[i] + 1.0f);
}

// ---------------- CSR build -----------------------------------------------
__global__ void k_scan1(int N) {
    __shared__ int sh[256];
    int i = blockIdx.x * 256 + threadIdx.x;
    int v = (i < N) ? g_deg[i] : 0;
    sh[threadIdx.x] = v;
    __syncthreads();
    int x = v;
#pragma unroll
    for (int o = 1; o < 256; o <<= 1) {
        int y = (threadIdx.x >= o) ? sh[threadIdx.x - o] : 0;
        __syncthreads();
        x += y; sh[threadIdx.x] = x;
        __syncthreads();
    }
    if (i < N) g_start[i] = x - v;
    if (threadIdx.x == 255) g_bsum[blockIdx.x] = x;
}
__global__ void k_scan2() {
    __shared__ int sh[256];
    int v = (threadIdx.x < NSCANB) ? g_bsum[threadIdx.x] : 0;
    sh[threadIdx.x] = v;
    __syncthreads();
    int x = v;
#pragma unroll
    for (int o = 1; o < 256; o <<= 1) {
        int y = (threadIdx.x >= o) ? sh[threadIdx.x - o] : 0;
        __syncthreads();
        x += y; sh[threadIdx.x] = x;
        __syncthreads();
    }
    if (threadIdx.x < NSCANB) g_bsum[threadIdx.x] = x - v;
}
__global__ void k_scan3(int N, int E) {
    int i = blockIdx.x * 256 + threadIdx.x;
    if (i < N) {
        int s = g_start[i] + g_bsum[i >> 8];
        g_start[i] = s;
        g_cursor[i] = s;
    }
    if (i == 0) g_start[N] = E;
}
__global__ void k_fill(const int *__restrict__ ei, int E) {
    int i = blockIdx.x * blockDim.x + threadIdx.x;
    if (i >= E) return;
    int d = ei[E + i];
    int pos = atomicAdd(&g_cursor[d], 1);
    g_csr[pos] = ei[i];
}

// ---------------- W prep --------------------------------------------------
__global__ void k_prepW(const float *__restrict__ W, __nv_bfloat16 *__restrict__ Bh,
                        __nv_bfloat16 *__restrict__ Bl, int K) {
    int i = blockIdx.x * blockDim.x + threadIdx.x;
    if (i >= K * HID) return;
    int k = i / HID, n = i % HID;
    float v = W[i];
    __nv_bfloat16 h = __float2bfloat16(v);
    __nv_bfloat16 l = __float2bfloat16(v - __bfloat162float(h));
    Bh[(size_t)n * K + k] = h;
    Bl[(size_t)n * K + k] = l;
}

// ==================== plain HMMA GEMM (conv2) ==============================
// C[M,128] = A[M,K] @ Bt^T  (raw, no bias/dinv)
__global__ void __launch_bounds__(256, 2)
hmma_gemm(const float *__restrict__ A,
          const __nv_bfloat16 *__restrict__ Bhg,
          const __nv_bfloat16 *__restrict__ Blg,
          float *__restrict__ C, int M, int K)
{
    extern __shared__ __align__(1024) char smem[];
    const uint32_t sb = s2u(smem);
    const int tid = threadIdx.x;
    const int wid = tid >> 5, lane = tid & 31;
    const int warp_m = wid & 3, warp_n = wid >> 2;
    const int bm0 = blockIdx.x * 128;

    const int alr = tid >> 1, alq = tid & 1;
    int arow = bm0 + alr; if (arow >= M) arow = M - 1;
    const float *Ar = A + (size_t)arow * K + alq * 16;
    const uint32_t a_sts = (uint32_t)(alr * ASTRIDE + alq * 32);

    const int bln = tid >> 1, blu = tid & 1;
    const __nv_bfloat16 *Bhr = Bhg + (size_t)bln * K + blu * 16;
    const __nv_bfloat16 *Blr = Blg + (size_t)bln * K + blu * 16;
    const uint32_t b_sts = (uint32_t)(bln * ASTRIDE + blu * 32);

    const int sub = lane >> 3, lr8 = lane & 7;
    uint32_t a_off[2], b_off[4];
#pragma unroll
    for (int mi = 0; mi < 2; ++mi) {
        int row = warp_m * 32 + mi * 16 + ((sub & 1) << 3) + lr8;
        a_off[mi] = (uint32_t)(row * ASTRIDE + ((sub >> 1) << 4));
    }
#pragma unroll
    for (int np = 0; np < 4; ++np) {
        int nr = warp_n * 64 + np * 16 + ((sub >> 1) << 3) + lr8;
        b_off[np] = (uint32_t)(nr * ASTRIDE + ((sub & 1) << 4));
    }

    float acc[2][8][4];
#pragma unroll
    for (int mi = 0; mi < 2; ++mi)
#pragma unroll
        for (int ni = 0; ni < 8; ++ni)
#pragma unroll
            for (int q = 0; q < 4; ++q) acc[mi][ni][q] = 0.f;

    const int NC = K / BK;
    float4 va0, va1, va2, va3;

    va0 = *(const float4 *)(Ar);
    va1 = *(const float4 *)(Ar + 4);
    va2 = *(const float4 *)(Ar + 8);
    va3 = *(const float4 *)(Ar + 12);
    {
        uint32_t s0 = sb + 2 * ABUF + b_sts;
        cpa16(s0,             Bhr);
        cpa16(s0 + 16,        Bhr + 8);
        cpa16(s0 + BBUF,      Blr);
        cpa16(s0 + BBUF + 16, Blr + 8);
        asm volatile("cp.async.commit_group;" ::: "memory");
    }
    {
        uint4 hv, lv;
        cvt8(va0, va1, hv, lv);
        *(uint4 *)(smem + a_sts)        = hv;
        *(uint4 *)(smem + ABUF + a_sts) = lv;
        cvt8(va2, va3, hv, lv);
        *(uint4 *)(smem + a_sts + 16)        = hv;
        *(uint4 *)(smem + ABUF + a_sts + 16) = lv;
    }
    asm volatile("cp.async.wait_group 0;" ::: "memory");
    __syncthreads();

    for (int c = 0; c < NC; ++c) {
        const uint32_t bo = (c & 1) ? (uint32_t)BUFSZ : 0u;
        const uint32_t bn = (c & 1) ? 0u : (uint32_t)BUFSZ;
        const bool more = (c + 1 < NC);
        if (more) {
            const int k1 = (c + 1) * BK;
            va0 = *(const float4 *)(Ar + k1);
            va1 = *(const float4 *)(Ar + k1 + 4);
            va2 = *(const float4 *)(Ar + k1 + 8);
            va3 = *(const float4 *)(Ar + k1 + 12);
            uint32_t s0 = sb + bn + 2 * ABUF + b_sts;
            cpa16(s0,             Bhr + k1);
            cpa16(s0 + 16,        Bhr + k1 + 8);
            cpa16(s0 + BBUF,      Blr + k1);
            cpa16(s0 + BBUF + 16, Blr + k1 + 8);
            asm volatile("cp.async.commit_group;" ::: "memory");
        }

#pragma unroll
        for (int ks = 0; ks < 2; ++ks) {
            uint32_t ahi[2][4], alo[2][4];
#pragma unroll
            for (int mi = 0; mi < 2; ++mi) {
                uint32_t ad = sb + bo + a_off[mi] + ks * 32;
                ldsm4(ahi[mi][0], ahi[mi][1], ahi[mi][2], ahi[mi][3], ad);
                ldsm4(alo[mi][0], alo[mi][1], alo[mi][2], alo[mi][3], ad + ABUF);
            }
#pragma unroll
            for (int np = 0; np < 4; ++np) {
                uint32_t bhi[2][2], blo[2][2];
                uint32_t bd = sb + bo + 2 * ABUF + b_off[np] + ks * 32;
                ldsm4(bhi[0][0], bhi[0][1], bhi[1][0], bhi[1][1], bd);
                ldsm4(blo[0][0], blo[0][1], blo[1][0], blo[1][1], bd + BBUF);
#pragma unroll
                for (int mi = 0; mi < 2; ++mi)
#pragma unroll
                    for (int h = 0; h < 2; ++h)
                        mma16816(acc[mi][np * 2 + h], ahi[mi], bhi[h]);
#pragma unroll
                for (int mi = 0; mi < 2; ++mi)
#pragma unroll
                    for (int h = 0; h < 2; ++h)
                        mma16816(acc[mi][np * 2 + h], ahi[mi], blo[h]);
#pragma unroll
                for (int mi = 0; mi < 2; ++mi)
#pragma unroll
                    for (int h = 0; h < 2; ++h)
                        mma16816(acc[mi][np * 2 + h], alo[mi], bhi[h]);
            }
        }

        if (more) {
            uint4 hv, lv;
            cvt8(va0, va1, hv, lv);
            *(uint4 *)(smem + bn + a_sts)        = hv;
            *(uint4 *)(smem + bn + ABUF + a_sts) = lv;
            cvt8(va2, va3, hv, lv);
            *(uint4 *)(smem + bn + a_sts + 16)        = hv;
            *(uint4 *)(smem + bn + ABUF + a_sts + 16) = lv;
            asm volatile("cp.async.wait_group 0;" ::: "memory");
        }
        __syncthreads();
    }

    const int gid = lane >> 2, qid = lane & 3;
#pragma unroll
    for (int mi = 0; mi < 2; ++mi) {
        int row0 = bm0 + warp_m * 32 + mi * 16 + gid;
        int row1 = row0 + 8;
#pragma unroll
        for (int ni = 0; ni < 8; ++ni) {
            int col = warp_n * 64 + ni * 8 + qid * 2;
            if (row0 < M)
                *(float2 *)&C[(size_t)row0 * HID + col] =
                    make_float2(acc[mi][ni][0], acc[mi][ni][1]);
            if (row1 < M)
                *(float2 *)&C[(size_t)row1 * HID + col] =
                    make_float2(acc[mi][ni][2], acc[mi][ni][3]);
        }
    }
}

// ==================== fused GEMM: hs = (x@Wemb + b_emb) @ Wc1 ==============
__global__ void __launch_bounds__(256, 2)
hmma_fused(const float *__restrict__ A,
           const __nv_bfloat16 *__restrict__ Bhg,
           const __nv_bfloat16 *__restrict__ Blg,
           const float *__restrict__ bias,
           const __nv_bfloat16 *__restrict__ W2h,
           const __nv_bfloat16 *__restrict__ W2l,
           float *__restrict__ C, int M, int K)
{
    extern __shared__ __align__(1024) char smem[];
    const uint32_t sb = s2u(smem);
    const int tid = threadIdx.x;
    const int wid = tid >> 5, lane = tid & 31;
    const int warp_m = wid & 3, warp_n = wid >> 2;
    const int bm0 = blockIdx.x * 128;

    const int alr = tid >> 1, alq = tid & 1;
    int arow = bm0 + alr; if (arow >= M) arow = M - 1;
    const float *Ar = A + (size_t)arow * K + alq * 16;
    const uint32_t a_sts = (uint32_t)(alr * ASTRIDE + alq * 32);

    const int bln = tid >> 1, blu = tid & 1;
    const __nv_bfloat16 *Bhr = Bhg + (size_t)bln * K + blu * 16;
    const __nv_bfloat16 *Blr = Blg + (size_t)bln * K + blu * 16;
    const __nv_bfloat16 *B2hr = W2h + (size_t)bln * HID + blu * 16;
    const __nv_bfloat16 *B2lr = W2l + (size_t)bln * HID + blu * 16;
    const uint32_t b_sts = (uint32_t)(bln * ASTRIDE + blu * 32);

    const int sub = lane >> 3, lr8 = lane & 7;
    uint32_t a_off[2], a2_off[2], b_off[4];
#pragma unroll
    for (int mi = 0; mi < 2; ++mi) {
        int row = warp_m * 32 + mi * 16 + ((sub & 1) << 3) + lr8;
        a_off[mi]  = (uint32_t)(row * ASTRIDE + ((sub >> 1) << 4));
        a2_off[mi] = (uint32_t)(row * TSTRIDE + ((sub >> 1) << 4));
    }
#pragma unroll
    for (int np = 0; np < 4; ++np) {
        int nr = warp_n * 64 + np * 16 + ((sub >> 1) << 3) + lr8;
        b_off[np] = (uint32_t)(nr * ASTRIDE + ((sub & 1) << 4));
    }

    float acc[2][8][4];
#pragma unroll
    for (int mi = 0; mi < 2; ++mi)
#pragma unroll
        for (int ni = 0; ni < 8; ++ni)
#pragma unroll
            for (int q = 0; q < 4; ++q) acc[mi][ni][q] = 0.f;

    const int NC = K / BK;
    float4 va0, va1, va2, va3;

    // ---- stage-1 prologue ----
    va0 = *(const float4 *)(Ar);
    va1 = *(const float4 *)(Ar + 4);
    va2 = *(const float4 *)(Ar + 8);
    va3 = *(const float4 *)(Ar + 12);
    {
        uint32_t s0 = sb + 2 * ABUF + b_sts;
        cpa16(s0,             Bhr);
        cpa16(s0 + 16,        Bhr + 8);
        cpa16(s0 + BBUF,      Blr);
        cpa16(s0 + BBUF + 16, Blr + 8);
        asm volatile("cp.async.commit_group;" ::: "memory");
    }
    {
        uint4 hv, lv;
        cvt8(va0, va1, hv, lv);
        *(uint4 *)(smem + a_sts)        = hv;
        *(uint4 *)(smem + ABUF + a_sts) = lv;
        cvt8(va2, va3, hv, lv);
        *(uint4 *)(smem + a_sts + 16)        = hv;
        *(uint4 *)(smem + ABUF + a_sts + 16) = lv;
    }
    asm volatile("cp.async.wait_group 0;" ::: "memory");
    __syncthreads();

    // ---- stage-1 main loop (K = INDIM) ----
    for (int c = 0; c < NC; ++c) {
        const uint32_t bo = (c & 1) ? (uint32_t)BUFSZ : 0u;
        const uint32_t bn = (c & 1) ? 0u : (uint32_t)BUFSZ;
        const bool more = (c + 1 < NC);
        if (more) {
            const int k1 = (c + 1) * BK;
            va0 = *(const float4 *)(Ar + k1);
            va1 = *(const float4 *)(Ar + k1 + 4);
            va2 = *(const float4 *)(Ar + k1 + 8);
            va3 = *(const float4 *)(Ar + k1 + 12);
            uint32_t s0 = sb + bn + 2 * ABUF + b_sts;
            cpa16(s0,             Bhr + k1);
            cpa16(s0 + 16,        Bhr + k1 + 8);
            cpa16(s0 + BBUF,      Blr + k1);
            cpa16(s0 + BBUF + 16, Blr + k1 + 8);
            asm volatile("cp.async.commit_group;" ::: "memory");
        }

#pragma unroll
        for (int ks = 0; ks < 2; ++ks) {
            uint32_t ahi[2][4], alo[2][4];
#pragma unroll
            for (int mi = 0; mi < 2; ++mi) {
                uint32_t ad = sb + bo + a_off[mi] + ks * 32;
                ldsm4(ahi[mi][0], ahi[mi][1], ahi[mi][2], ahi[mi][3], ad);
                ldsm4(alo[mi][0], alo[mi][1], alo[mi][2], alo[mi][3], ad + ABUF);
            }
#pragma unroll
            for (int np = 0; np < 4; ++np) {
                uint32_t bhi[2][2], blo[2][2];
                uint32_t bd = sb + bo + 2 * ABUF + b_off[np] + ks * 32;
                ldsm4(bhi[0][0], bhi[0][1], bhi[1][0], bhi[1][1], bd);
                ldsm4(blo[0][0], blo[0][1], blo[1][0], blo[1][1], bd + BBUF);
#pragma unroll
                for (int mi = 0; mi < 2; ++mi)
#pragma unroll
                    for (int h = 0; h < 2; ++h)
                        mma16816(acc[mi][np * 2 + h], ahi[mi], bhi[h]);
#pragma unroll
                for (int mi = 0; mi < 2; ++mi)
#pragma unroll
                    for (int h = 0; h < 2; ++h)
                        mma16816(acc[mi][np * 2 + h], ahi[mi], blo[h]);
#pragma unroll
                for (int mi = 0; mi < 2; ++mi)
#pragma unroll
                    for (int h = 0; h < 2; ++h)
                        mma16816(acc[mi][np * 2 + h], alo[mi], bhi[h]);
            }
        }

        if (more) {
            uint4 hv, lv;
            cvt8(va0, va1, hv, lv);
            *(uint4 *)(smem + bn + a_sts)        = hv;
            *(uint4 *)(smem + bn + ABUF + a_sts) = lv;
            cvt8(va2, va3, hv, lv);
            *(uint4 *)(smem + bn + a_sts + 16)        = hv;
            *(uint4 *)(smem + bn + ABUF + a_sts + 16) = lv;
            asm volatile("cp.async.wait_group 0;" ::: "memory");
        }
        __syncthreads();
    }

    // ---- prefetch stage-2 B chunks 0,1 (B2 region overlaps old buffer0) ----
    {
        uint32_t s0 = sb + b_sts;                 // buf0
        cpa16(s0,              B2hr);
        cpa16(s0 + 16,         B2hr + 8);
        cpa16(s0 + 10240,      B2lr);
        cpa16(s0 + 10240 + 16, B2lr + 8);
        asm volatile("cp.async.commit_group;" ::: "memory");
        uint32_t s1 = sb + B2BUF + b_sts;         // buf1
        cpa16(s1,              B2hr + 32);
        cpa16(s1 + 16,         B2hr + 32 + 8);
        cpa16(s1 + 10240,      B2lr + 32);
        cpa16(s1 + 10240 + 16, B2lr + 32 + 8);
        asm volatile("cp.async.commit_group;" ::: "memory");
    }

    // ---- epilogue-1: T = acc + bias -> bf16 hi/lo in SMEM ----
    const int gid = lane >> 2, qid = lane & 3;
#pragma unroll
    for (int mi = 0; mi < 2; ++mi) {
        int r0 = warp_m * 32 + mi * 16 + gid;      // local tile rows
        int r1 = r0 + 8;
#pragma unroll
        for (int ni = 0; ni < 8; ++ni) {
            int col = warp_n * 64 + ni * 8 + qid * 2;
            float b0 = bias[col], b1 = bias[col + 1];
            float t0 = acc[mi][ni][0] + b0, t1 = acc[mi][ni][1] + b1;
            float t2 = acc[mi][ni][2] + b0, t3 = acc[mi][ni][3] + b1;
            __nv_bfloat162 h01 = __floats2bfloat162_rn(t0, t1);
            __nv_bfloat162 l01 = __floats2bfloat162_rn(t0 - __bfloat162float(h01.x),
                                                       t1 - __bfloat162float(h01.y));
            __nv_bfloat162 h23 = __floats2bfloat162_rn(t2, t3);
            __nv_bfloat162 l23 = __floats2bfloat162_rn(t2 - __bfloat162float(h23.x),
                                                       t3 - __bfloat162float(h23.y));
            *(uint32_t *)(smem + T_HI + r0 * TSTRIDE + col * 2) = *(uint32_t *)&h01;
            *(uint32_t *)(smem + T_LO + r0 * TSTRIDE + col * 2) = *(uint32_t *)&l01;
            *(uint32_t *)(smem + T_HI + r1 * TSTRIDE + col * 2) = *(uint32_t *)&h23;
            *(uint32_t *)(smem + T_LO + r1 * TSTRIDE + col * 2) = *(uint32_t *)&l23;
        }
    }
    // zero acc for stage 2
#pragma unroll
    for (int mi = 0; mi < 2; ++mi)
#pragma unroll
        for (int ni = 0; ni < 8; ++ni)
#pragma unroll
            for (int q = 0; q < 4; ++q) acc[mi][ni][q] = 0.f;
    __syncthreads();

    // ---- stage-2 loop (K2 = HID = 128, 4 chunks) ----
#pragma unroll
    for (int c2 = 0; c2 < 4; ++c2) {
        if (c2 == 3)
            asm volatile("cp.async.wait_group 0;" ::: "memory");
        else
            asm volatile("cp.async.wait_group 1;" ::: "memory");
        __syncthreads();

        const uint32_t bb = (uint32_t)((c2 & 1) * B2BUF);
#pragma unroll
        for (int ks = 0; ks < 2; ++ks) {
            uint32_t ahi[2][4], alo[2][4];
#pragma unroll
            for (int mi = 0; mi < 2; ++mi) {
                uint32_t ad = sb + T_HI + a2_off[mi] + c2 * 64 + ks * 32;
                ldsm4(ahi[mi][0], ahi[mi][1], ahi[mi][2], ahi[mi][3], ad);
                ldsm4(alo[mi][0], alo[mi][1], alo[mi][2], alo[mi][3],
                      ad + (T_LO - T_HI));
            }
#pragma unroll
            for (int np = 0; np < 4; ++np) {
                uint32_t bhi[2][2], blo[2][2];
                uint32_t bd = sb + bb + b_off[np] + ks * 32;
                ldsm4(bhi[0][0], bhi[0][1], bhi[1][0], bhi[1][1], bd);
                ldsm4(blo[0][0], blo[0][1], blo[1][0], blo[1][1], bd + 10240);
#pragma unroll
                for (int mi = 0; mi < 2; ++mi)
#pragma unroll
                    for (int h = 0; h < 2; ++h)
                        mma16816(acc[mi][np * 2 + h], ahi[mi], bhi[h]);
#pragma unroll
                for (int mi = 0; mi < 2; ++mi)
#pragma unroll
                    for (int h = 0; h < 2; ++h)
                        mma16816(acc[mi][np * 2 + h], ahi[mi], blo[h]);
#pragma unroll
                for (int mi = 0; mi < 2; ++mi)
#pragma unroll
                    for (int h = 0; h < 2; ++h)
                        mma16816(acc[mi][np * 2 + h], alo[mi], bhi[h]);
            }
        }

        if (c2 < 2) {
            __syncthreads();
            const int kc = (c2 + 2) * 32;
            uint32_t s0 = sb + (uint32_t)((c2 & 1) * B2BUF) + b_sts;
            cpa16(s0,              B2hr + kc);
            cpa16(s0 + 16,         B2hr + kc + 8);
            cpa16(s0 + 10240,      B2lr + kc);
            cpa16(s0 + 10240 + 16, B2lr + kc + 8);
            asm volatile("cp.async.commit_group;" ::: "memory");
        }
    }

    // ---- epilogue-2: raw hs out (dinv applied later in k_agg) ----
#pragma unroll
    for (int mi = 0; mi < 2; ++mi) {
        int row0 = bm0 + warp_m * 32 + mi * 16 + gid;
        int row1 = row0 + 8;
#pragma unroll
        for (int ni = 0; ni < 8; ++ni) {
            int col = warp_n * 64 + ni * 8 + qid * 2;
            if (row0 < M)
                *(float2 *)&C[(size_t)row0 * HID + col] =
                    make_float2(acc[mi][ni][0], acc[mi][ni][1]);
            if (row1 < M)
                *(float2 *)&C[(size_t)row1 * HID + col] =
                    make_float2(acc[mi][ni][2], acc[mi][ni][3]);
        }
    }
}

// ---------------- CSR aggregate: warp per node -----------------------------
// hs is RAW (h@W).  out = dinv_d*(sum_s dinv_s*hs_s + dinv_d*hs_d) + bias
__global__ void __launch_bounds__(256)
k_agg(const float *__restrict__ hs, const float *__restrict__ bias,
      float *__restrict__ outp, const int *__restrict__ batch,
      float *__restrict__ pool, int relu, int pool_mode, int N)
{
    int node = (blockIdx.x * blockDim.x + threadIdx.x) >> 5;
    if (node >= N) return;
    int lane = threadIdx.x & 31;
    int c = lane * 4;

    float dv = g_dinv[node];
    int e0 = g_start[node], e1 = g_start[node + 1];
    float4 s = *(const float4 *)&hs[(size_t)node * HID + c];
    float4 acc = make_float4(dv * s.x, dv * s.y, dv * s.z, dv * s.w);

    int e = e0;
    for (; e + 4 <= e1; e += 4) {
        int i0 = g_csr[e], i1 = g_csr[e + 1], i2 = g_csr[e + 2], i3 = g_csr[e + 3];
        float w0 = g_dinv[i0], w1 = g_dinv[i1], w2 = g_dinv[i2], w3 = g_dinv[i3];
        float4 v0 = *(const float4 *)&hs[(size_t)i0 * HID + c];
        float4 v1 = *(const float4 *)&hs[(size_t)i1 * HID + c];
        float4 v2 = *(const float4 *)&hs[(size_t)i2 * HID + c];
        float4 v3 = *(const float4 *)&hs[(size_t)i3 * HID + c];
        acc.x = fmaf(w0, v0.x, fmaf(w1, v1.x, fmaf(w2, v2.x, fmaf(w3, v3.x, acc.x))));
        acc.y = fmaf(w0, v0.y, fmaf(w1, v1.y, fmaf(w2, v2.y, fmaf(w3, v3.y, acc.y))));
        acc.z = fmaf(w0, v0.z, fmaf(w1, v1.z, fmaf(w2, v2.z, fmaf(w3, v3.z, acc.z))));
        acc.w = fmaf(w0, v0.w, fmaf(w1, v1.w, fmaf(w2, v2.w, fmaf(w3, v3.w, acc.w))));
    }
    for (; e < e1; ++e) {
        int i0 = g_csr[e];
        float w0 = g_dinv[i0];
        float4 v0 = *(const float4 *)&hs[(size_t)i0 * HID + c];
        acc.x = fmaf(w0, v0.x, acc.x);
        acc.y = fmaf(w0, v0.y, acc.y);
        acc.z = fmaf(w0, v0.z, acc.z);
        acc.w = fmaf(w0, v0.w, acc.w);
    }

    float4 b = *(const float4 *)&bias[c];
    float4 o;
    o.x = fmaf(dv, acc.x, b.x);
    o.y = fmaf(dv, acc.y, b.y);
    o.z = fmaf(dv, acc.z, b.z);
    o.w = fmaf(dv, acc.w, b.w);
    if (relu) {
        o.x = fmaxf(o.x, 0.f); o.y = fmaxf(o.y, 0.f);
        o.z = fmaxf(o.z, 0.f); o.w = fmaxf(o.w, 0.f);
    }
    if (pool_mode) {
        int g = batch[node];
        red4(&pool[(size_t)g * HID + c], o);
        if (lane == 0) atomicAdd(&pool[NGRAPH * HID + g], 1.0f);
    } else {
        *(float4 *)&outp[(size_t)node * HID + c] = o;
    }
}

// ---------------- head MLP -------------------------------------------------
__global__ void k_head(const float *__restrict__ pool,
                       const float *__restrict__ W1, const float *__restrict__ b1,
                       const float *__restrict__ W2, const float *__restrict__ b2,
                       float *__restrict__ out)
{
    __shared__ float gv[HID];
    __shared__ float hid[HID];
    int g = blockIdx.x, t = threadIdx.x;
    float cnt = fmaxf(pool[NGRAPH * HID + g], 1.0f);
    gv[t] = pool[(size_t)g * HID + t] / cnt;
    __syncthreads();
    float acc = b1[t];
#pragma unroll 8
    for (int c = 0; c < HID; ++c) acc = fmaf(gv[c], W1[c * HID + t], acc);
    hid[t] = fmaxf(acc, 0.f);
    __syncthreads();
    if (t < NCLS) {
        float o = b2[t];
#pragma unroll 8
        for (int hh = 0; hh < HID; ++hh) o = fmaf(hid[hh], W2[hh * NCLS + t], o);
        out[g * NCLS + t] = o;
    }
}

// ---------------- launcher -------------------------------------------------
extern "C" void kernel_launch(void *const *d_in, const int *in_sizes, int n_in,
                              void *d_out, int out_size)
{
    const float *x     = (const float *)d_in[0];
    const int   *ei    = (const int *)d_in[1];
    const int   *batch = (const int *)d_in[2];
    const float *W_emb = (const float *)d_in[3], *b_emb = (const float *)d_in[4];
    const float *W_c1  = (const float *)d_in[5], *b_c1  = (const float *)d_in[6];
    const float *W_c2  = (const float *)d_in[7], *b_c2  = (const float *)d_in[8];
    const float *W_l1  = (const float *)d_in[9], *b_l1  = (const float *)d_in[10];
    const float *W_l2  = (const float *)d_in[11], *b_l2 = (const float *)d_in[12];
    float *out = (float *)d_out;

    const int E = in_sizes[1] / 2;
    const int N = in_sizes[2];
    const int K_IN = in_sizes[0] / N;

    static float *p_h = nullptr, *p_hs = nullptr, *p_pool = nullptr;
    static int *p_deg = nullptr;
    static __nv_bfloat16 *p_We_h, *p_We_l, *p_W1_h, *p_W1_l, *p_W2_h, *p_W2_l;
    static cudaStream_t s2 = nullptr;
    static cudaEvent_t evFork = nullptr, evJoin = nullptr;
    if (!p_h) {
        cudaGetSymbolAddress((void **)&p_h,    g_h);
        cudaGetSymbolAddress((void **)&p_hs,   g_hs);
        cudaGetSymbolAddress((void **)&p_pool, g_pool);
        cudaGetSymbolAddress((void **)&p_deg,  g_deg);
        cudaGetSymbolAddress((void **)&p_We_h, g_Wemb_h);
        cudaGetSymbolAddress((void **)&p_We_l, g_Wemb_l);
        cudaGetSymbolAddress((void **)&p_W1_h, g_Wc1_h);
        cudaGetSymbolAddress((void **)&p_W1_l, g_Wc1_l);
        cudaGetSymbolAddress((void **)&p_W2_h, g_Wc2_h);
        cudaGetSymbolAddress((void **)&p_W2_l, g_Wc2_l);
        cudaFuncSetAttribute(hmma_gemm,
                             cudaFuncAttributeMaxDynamicSharedMemorySize, MMA_SMEM);
        cudaFuncSetAttribute(hmma_fused,
                             cudaFuncAttributeMaxDynamicSharedMemorySize, FUSED_SMEM);
        cudaStreamCreateWithFlags(&s2, cudaStreamNonBlocking);
        cudaEventCreateWithFlags(&evFork, cudaEventDisableTiming);
        cudaEventCreateWithFlags(&evJoin, cudaEventDisableTiming);
    }

    const int mma_grid  = (N + 127) / 128;
    const int agg_grid  = (N * 32 + 255) / 256;

    // ---- fork: side chain on s2 (needed only by k_agg) ----
    cudaEventRecord(evFork, 0);
    cudaStreamWaitEvent(s2, evFork, 0);

    k_zero_deg<<<(N + 255) / 256, 256, 0, s2>>>(p_deg, N);
    k_deg <<<(E + 255) / 256, 256, 0, s2>>>(ei, E);
    k_dinv<<<(N + 255) / 256, 256, 0, s2>>>(N);
    k_scan1<<<NSCANB, 256, 0, s2>>>(N);
    k_scan2<<<1, 256, 0, s2>>>();
    k_scan3<<<(N + 255) / 256, 256, 0, s2>>>(N, E);
    k_fill <<<(E + 255) / 256, 256, 0, s2>>>(ei, E);
    k_prepW<<<(HID * HID + 255) / 256, 256, 0, s2>>>(W_c2, p_W2_h, p_W2_l, HID);
    k_zero4<<<(NGRAPH * (HID + 1) / 4 + 255) / 256, 256, 0, s2>>>(
        (float4 *)p_pool, NGRAPH * (HID + 1) / 4);

    // main chain: weight prep + fused embedding+conv1 matmul
    k_prepW<<<(K_IN * HID + 255) / 256, 256>>>(W_emb, p_We_h, p_We_l, K_IN);
    k_prepW<<<(HID * HID + 255) / 256, 256>>>(W_c1, p_W1_h, p_W1_l, HID);
    hmma_fused<<<mma_grid, 256, FUSED_SMEM>>>(x, p_We_h, p_We_l, b_emb,
                                              p_W1_h, p_W1_l, p_hs, N, K_IN);

    // ---- join (k_agg needs CSR + dinv) ----
    cudaEventRecord(evJoin, s2);
    cudaStreamWaitEvent(0, evJoin, 0);

    // conv1 aggregate -> h1
    k_agg<<<agg_grid, 256>>>(p_hs, b_c1, p_h, nullptr, nullptr, 1, 0, N);

    // conv2 matmul (raw) + fused agg+pool
    hmma_gemm<<<mma_grid, 256, MMA_SMEM>>>(p_h, p_W2_h, p_W2_l, p_hs, N, HID);
    k_agg<<<agg_grid, 256>>>(p_hs, b_c2, nullptr, batch, p_pool, 0, 1, N);

    // head
    k_head<<<NGRAPH, HID>>>(p_pool, W_l1, b_l1, W_l2, b_l2, out);
}